// round 14
// baseline (speedup 1.0000x reference)
#include <cuda_runtime.h>
#include <math.h>
#include <stdint.h>

// Router: logits = x @ W^T ; softmax ; top-8 ; scatter gates + one-hot map.
// x: [T, 2048] fp32, W: [64, 2048] fp32
// out: [2*T*64] fp32 : first T*64 = dense gates, next T*64 = one-hot map
//
// R13: parallelism + pipeline de-duplication.
//  - 512 threads/CTA (grid=256, 2 CTAs/SM -> 2048 thr/SM, 2x warps in flight)
//  - W pre-split ONCE to global uint2(hi,lo) by a tiny pre-kernel; mainloop
//    fetches W tiles via cp.async (no W split / staging in the hot loop)
//  - interleaved (hi,lo) smem -> LDS.64 fragment loads (half the LDS count)
// Epilogue/guard/Kahan-repair identical to the R12-validated path.

#define HID   2048
#define NEXP  64
#define TOPK  8
#define BM    64
#define BK    32
#define NTHREADS 512
#define KS    36                      // padded k-stride in uint2 units
#define FLT_MIN_POS 1.17549435e-38f
#define EXP_CUT     87.336544f
#define GUARD       0.015f
#define GUARD_CUT   0.015f

__device__ uint2 g_whl[NEXP][HID];    // W pre-split to tf32 (hi,lo)

struct GemmBufs {
    uint2 xhl[2][BM][KS];             // x (hi,lo) interleaved
    uint2 whl[2][NEXP][KS];           // w (hi,lo) interleaved
};
struct EpiBufs {
    float  lg[BM][NEXP + 1];
    float  qv[BM][NEXP + 1];
    float  red[8][NEXP];
    float  exlog[NEXP];
    int    flagCnt;
    int    flagRows[BM];
};
union SmemU { GemmBufs g; EpiBufs e; };

__device__ __forceinline__ void split_tf32(float v, uint32_t &hi, uint32_t &lo)
{
    asm("cvt.rna.tf32.f32 %0, %1;" : "=r"(hi) : "f"(v));
    float r = v - __uint_as_float(hi);
    asm("cvt.rna.tf32.f32 %0, %1;" : "=r"(lo) : "f"(r));
}

__device__ __forceinline__ void mma_tf32(float &c0, float &c1, float &c2, float &c3,
                                         uint32_t a0, uint32_t a1, uint32_t a2, uint32_t a3,
                                         uint32_t b0, uint32_t b1)
{
    asm volatile(
        "mma.sync.aligned.m16n8k8.row.col.f32.tf32.tf32.f32 "
        "{%0,%1,%2,%3}, {%4,%5,%6,%7}, {%8,%9}, {%0,%1,%2,%3};\n"
        : "+f"(c0), "+f"(c1), "+f"(c2), "+f"(c3)
        : "r"(a0), "r"(a1), "r"(a2), "r"(a3), "r"(b0), "r"(b1));
}

// TwoProd + Kahan step (validated R12): effective sum = s - c.
__device__ __forceinline__ void comp_fma(float xv, float wv, float &s, float &c)
{
    float p = xv * wv;
    float e = fmaf(xv, wv, -p);
    float y = p - c;
    float t = s + y;
    c = (t - s) - y;
    c -= e;
    s = t;
}

#define CP_ASYNC16(dst_u32, src_ptr) \
    asm volatile("cp.async.cg.shared.global [%0], [%1], 16;" \
                 :: "r"(dst_u32), "l"(src_ptr))
#define CP_COMMIT() asm volatile("cp.async.commit_group;")
#define CP_WAIT0()  asm volatile("cp.async.wait_group 0;")

__global__ void split_w_kernel(const float* __restrict__ w)
{
    int idx = blockIdx.x * blockDim.x + threadIdx.x;   // 131072 total
    if (idx < NEXP * HID) {
        uint32_t hi, lo;
        split_tf32(w[idx], hi, lo);
        ((uint2*)g_whl)[idx] = make_uint2(hi, lo);
    }
}

__global__ __launch_bounds__(NTHREADS, 2)
void router_kernel(const float* __restrict__ x,
                   const float* __restrict__ w,
                   float* __restrict__ out,
                   int T)
{
    extern __shared__ char smraw[];
    SmemU& S = *reinterpret_cast<SmemU*>(smraw);

    const int tid  = threadIdx.x;
    const int lane = tid & 31;
    const int wid  = tid >> 5;          // 16 warps
    const int rg   = wid & 3;           // rows rg*16 .. +15
    const int cg   = wid >> 2;          // experts cg*16 .. +15 (2 n-tiles)
    const int lr   = lane >> 2;         // 0..7
    const int lc   = lane & 3;          // 0..3
    const int rowBase = blockIdx.x * BM;

    float accP[2][4], accQ[2][4];
#pragma unroll
    for (int i = 0; i < 2; i++)
#pragma unroll
        for (int j = 0; j < 4; j++) { accP[i][j] = 0.0f; accQ[i][j] = 0.0f; }

    // x tile: 64 rows x 8 float4 = 512 float4, one per thread.
    const int xr_ = tid >> 3, xq_ = tid & 7;
    const float4* __restrict__ xg = (const float4*)x;   // row stride 512
    const float4* __restrict__ wg = (const float4*)w;

    // W tile via cp.async: 1024 x 16B chunks, two per thread.
    const int c0 = tid, c1 = tid + NTHREADS;
    const int wrow0 = c0 >> 4, wq0 = (c0 & 15) * 2;
    const int wrow1 = c1 >> 4, wq1 = (c1 & 15) * 2;

    // ── Prologue: stage 0 ───────────────────────────────────────────────
    {
        uint32_t d0 = (uint32_t)__cvta_generic_to_shared(&S.g.whl[0][wrow0][wq0]);
        uint32_t d1 = (uint32_t)__cvta_generic_to_shared(&S.g.whl[0][wrow1][wq1]);
        CP_ASYNC16(d0, &g_whl[wrow0][wq0]);
        CP_ASYNC16(d1, &g_whl[wrow1][wq1]);
        CP_COMMIT();

        float4 v = xg[(size_t)(rowBase + xr_) * (HID / 4) + xq_];
        uint32_t h0,l0,h1,l1,h2,l2,h3,l3;
        split_tf32(v.x,h0,l0); split_tf32(v.y,h1,l1);
        split_tf32(v.z,h2,l2); split_tf32(v.w,h3,l3);
        *(uint4*)&S.g.xhl[0][xr_][xq_ * 4]     = make_uint4(h0,l0,h1,l1);
        *(uint4*)&S.g.xhl[0][xr_][xq_ * 4 + 2] = make_uint4(h2,l2,h3,l3);
        CP_WAIT0();
    }
    __syncthreads();

    const int NT = HID / BK;            // 64 K-tiles
    float4 xnext;
    for (int t = 0; t < NT; t++) {
        const int st = t & 1;
        const int sn = st ^ 1;

        if (t + 1 < NT) {
            const int ko = (t + 1) * BK;          // k offset in elements
            // kick W(t+1) into the other stage (overlaps consume below)
            uint32_t d0 = (uint32_t)__cvta_generic_to_shared(&S.g.whl[sn][wrow0][wq0]);
            uint32_t d1 = (uint32_t)__cvta_generic_to_shared(&S.g.whl[sn][wrow1][wq1]);
            CP_ASYNC16(d0, &g_whl[wrow0][ko + wq0]);
            CP_ASYNC16(d1, &g_whl[wrow1][ko + wq1]);
            CP_COMMIT();
            xnext = xg[(size_t)(rowBase + xr_) * (HID / 4) + (ko / 4) + xq_];
        }

        // Consume stage st: LDS.64 -> HMMA
#pragma unroll
        for (int ks_ = 0; ks_ < BK / 8; ks_++) {
            const int kb  = ks_ * 8;
            const int ra0 = rg * 16 + lr, ra1 = ra0 + 8;

            uint2 a0 = S.g.xhl[st][ra0][kb + lc];
            uint2 a1 = S.g.xhl[st][ra1][kb + lc];
            uint2 a2 = S.g.xhl[st][ra0][kb + lc + 4];
            uint2 a3 = S.g.xhl[st][ra1][kb + lc + 4];

            uint2 b0[2], b1[2];
#pragma unroll
            for (int nt = 0; nt < 2; nt++) {
                const int nr = cg * 16 + nt * 8 + lr;
                b0[nt] = S.g.whl[st][nr][kb + lc];
                b1[nt] = S.g.whl[st][nr][kb + lc + 4];
            }
#pragma unroll
            for (int nt = 0; nt < 2; nt++)
                mma_tf32(accP[nt][0], accP[nt][1], accP[nt][2], accP[nt][3],
                         a0.x, a1.x, a2.x, a3.x, b0[nt].x, b1[nt].x);
#pragma unroll
            for (int nt = 0; nt < 2; nt++)
                mma_tf32(accQ[nt][0], accQ[nt][1], accQ[nt][2], accQ[nt][3],
                         a0.x, a1.x, a2.x, a3.x, b0[nt].y, b1[nt].y);
#pragma unroll
            for (int nt = 0; nt < 2; nt++)
                mma_tf32(accQ[nt][0], accQ[nt][1], accQ[nt][2], accQ[nt][3],
                         a0.y, a1.y, a2.y, a3.y, b0[nt].x, b1[nt].x);
        }

        if (t + 1 < NT) {
            uint32_t h0,l0,h1,l1,h2,l2,h3,l3;
            split_tf32(xnext.x,h0,l0); split_tf32(xnext.y,h1,l1);
            split_tf32(xnext.z,h2,l2); split_tf32(xnext.w,h3,l3);
            *(uint4*)&S.g.xhl[sn][xr_][xq_ * 4]     = make_uint4(h0,l0,h1,l1);
            *(uint4*)&S.g.xhl[sn][xr_][xq_ * 4 + 2] = make_uint4(h2,l2,h3,l3);
            CP_WAIT0();
        }
        __syncthreads();
    }

    // Dump merged accumulators -> logits (overlays dead GEMM buffers).
#pragma unroll
    for (int nt = 0; nt < 2; nt++) {
        const int col = cg * 16 + nt * 8 + lc * 2;
        S.e.lg[rg * 16 + lr][col]         = accP[nt][0] + accQ[nt][0];
        S.e.lg[rg * 16 + lr][col + 1]     = accP[nt][1] + accQ[nt][1];
        S.e.lg[rg * 16 + lr + 8][col]     = accP[nt][2] + accQ[nt][2];
        S.e.lg[rg * 16 + lr + 8][col + 1] = accP[nt][3] + accQ[nt][3];
    }
    if (tid == 0) S.e.flagCnt = 0;
    __syncthreads();

    // ── Fast epilogue: one thread per row (validated R7..R12) ───────────
    if (tid < BM) {
        const int row = rowBase + tid;

        float m = -1e30f;
#pragma unroll
        for (int e = 0; e < NEXP; e++) m = fmaxf(m, S.e.lg[tid][e]);

        float s = 0.0f;
#pragma unroll
        for (int e = 0; e < NEXP; e++) {
            float d = S.e.lg[tid][e] - m;
            S.e.lg[tid][e] = d;
            float p = expf(d);
            if (p < FLT_MIN_POS) p = 0.0f;       // exp flush (R2->R3 evidence)
            S.e.qv[tid][e] = p;
            s += p;
        }

#pragma unroll
        for (int e = 0; e < NEXP; e++) {
            float q = __fdiv_rn(S.e.qv[tid][e], s);
            if (q < FLT_MIN_POS) q = 0.0f;       // division flush band
            S.e.qv[tid][e] = q;
        }

        unsigned long long mask = 0ull;
        for (int k = 0; k < TOPK; k++) {
            float bv = -1.0f; int bi = 0;
            for (int e = 0; e < NEXP; e++) {
                float v = S.e.qv[tid][e];
                if (!((mask >> e) & 1ull) && v > bv) { bv = v; bi = e; }
            }
            mask |= (1ull << bi);
        }

        // Robustness guard
        int nA = 0;
        float d8 = 1e30f, d9 = -1e30f;
#pragma unroll
        for (int e = 0; e < NEXP; e++) {
            bool pos = S.e.qv[tid][e] > 0.0f;
            bool sel = (mask >> e) & 1ull;
            if (pos) {
                nA++;
                if (sel)  d8 = fminf(d8, S.e.lg[tid][e]);
                else      d9 = fmaxf(d9, S.e.lg[tid][e]);
            }
        }
        bool flag = false;
        if (d9 > -1e29f && (d8 - d9) < GUARD) flag = true;
        if (nA <= 8) {
            float c = logf(s) - EXP_CUT;
#pragma unroll
            for (int e = 0; e < NEXP; e++)
                if (fabsf(S.e.lg[tid][e] - c) < GUARD_CUT) flag = true;
        }

        if (!flag) {
            float* __restrict__ gout = out + (size_t)row * NEXP;
            float* __restrict__ mout = out + (size_t)T * NEXP + (size_t)row * NEXP;
#pragma unroll
            for (int e = 0; e < NEXP; e++) {
                const bool sel = (mask >> e) & 1ull;
                gout[e] = sel ? S.e.qv[tid][e] : 0.0f;
                mout[e] = sel ? 1.0f : 0.0f;
            }
        } else {
            S.e.flagRows[atomicAdd(&S.e.flagCnt, 1)] = tid;
        }
    }
    __syncthreads();

    // ── High-precision fp32 repair (TwoProd + Kahan, validated R12) ─────
    const int nf = S.e.flagCnt;
    for (int r = 0; r < nf; r++) {
        const int lrow = S.e.flagRows[r];
        const int row  = rowBase + lrow;
        const int e    = tid & 63;
        const int ch   = tid >> 6;              // 8 chunks of 256 elements

        const float4* xr = xg + (size_t)row * (HID / 4) + ch * 64;
        const float4* wr = wg + (size_t)e   * (HID / 4) + ch * 64;
        float s0 = 0.f, cc0 = 0.f, s1 = 0.f, cc1 = 0.f;
        float s2 = 0.f, cc2 = 0.f, s3 = 0.f, cc3 = 0.f;
#pragma unroll 4
        for (int i = 0; i < 64; i++) {
            float4 xv = xr[i], wv = wr[i];
            comp_fma(xv.x, wv.x, s0, cc0);
            comp_fma(xv.y, wv.y, s1, cc1);
            comp_fma(xv.z, wv.z, s2, cc2);
            comp_fma(xv.w, wv.w, s3, cc3);
        }
        S.e.red[ch][e] = ((s0 - cc0) + (s1 - cc1)) + ((s2 - cc2) + (s3 - cc3));
        __syncthreads();
        if (tid < NEXP) {
            float acc = 0.0f;
#pragma unroll
            for (int c = 0; c < 8; c++) acc += S.e.red[c][tid];
            S.e.exlog[tid] = acc;
        }
        __syncthreads();

        if (tid == 0) {
            float m = -1e30f;
            for (int ee = 0; ee < NEXP; ee++) m = fmaxf(m, S.e.exlog[ee]);
            float s = 0.0f;
            float pbuf[NEXP];
            for (int ee = 0; ee < NEXP; ee++) {
                float p = expf(S.e.exlog[ee] - m);
                if (p < FLT_MIN_POS) p = 0.0f;
                pbuf[ee] = p;
                s += p;
            }
            for (int ee = 0; ee < NEXP; ee++) {
                float q = __fdiv_rn(pbuf[ee], s);
                if (q < FLT_MIN_POS) q = 0.0f;
                pbuf[ee] = q;
            }
            unsigned long long mask = 0ull;
            for (int k = 0; k < TOPK; k++) {
                float bv = -1.0f; int bi = 0;
                for (int ee = 0; ee < NEXP; ee++) {
                    float v = pbuf[ee];
                    if (!((mask >> ee) & 1ull) && v > bv) { bv = v; bi = ee; }
                }
                mask |= (1ull << bi);
            }
            float* __restrict__ gout = out + (size_t)row * NEXP;
            float* __restrict__ mout = out + (size_t)T * NEXP + (size_t)row * NEXP;
            for (int ee = 0; ee < NEXP; ee++) {
                const bool sel = (mask >> ee) & 1ull;
                gout[ee] = sel ? pbuf[ee] : 0.0f;
                mout[ee] = sel ? 1.0f : 0.0f;
            }
        }
        __syncthreads();
    }
}

extern "C" void kernel_launch(void* const* d_in, const int* in_sizes, int n_in,
                              void* d_out, int out_size)
{
    const float* x = (const float*)d_in[0];
    const float* w = (const float*)d_in[1];
    float* out = (float*)d_out;
    const int T = in_sizes[0] / HID;       // 16384
    const int grid = T / BM;               // 256

    split_w_kernel<<<(NEXP * HID + 511) / 512, 512>>>(w);

    const int smem = (int)sizeof(SmemU);   // ~73 KB
    cudaFuncSetAttribute(router_kernel,
                         cudaFuncAttributeMaxDynamicSharedMemorySize, smem);
    router_kernel<<<grid, NTHREADS, smem>>>(x, w, out, T);
}

// round 15
// speedup vs baseline: 1.1677x; 1.1677x over previous
#include <cuda_runtime.h>
#include <math.h>
#include <stdint.h>

// Router: logits = x @ W^T ; softmax ; top-8 ; scatter gates + one-hot map.
// x: [T, 2048] fp32, W: [64, 2048] fp32
// out: [2*T*64] fp32 : first T*64 = dense gates, next T*64 = one-hot map
//
// R14 = R12 (202us, validated) + ONE change: W pre-split once to global
// (hi,lo) planes by a pre-kernel; mainloop fetches W tiles via cp.async into
// the same conflict-free separate-plane smem layout. x path, consume loop,
// epilogue, guard and Kahan repair are byte-identical to R12.

#define HID   2048
#define NEXP  64
#define TOPK  8
#define BM    64
#define BK    32
#define NTHREADS 256
#define KS    36                      // padded k-stride (bank-stagger, R12-proven)
#define FLT_MIN_POS 1.17549435e-38f
#define EXP_CUT     87.336544f
#define GUARD       0.015f
#define GUARD_CUT   0.015f

__device__ uint32_t g_wh[NEXP][HID];  // W tf32 hi plane (512 KB, L2-resident)
__device__ uint32_t g_wl[NEXP][HID];  // W tf32 lo plane

struct GemmBufs {
    uint32_t xh[2][BM][KS];
    uint32_t xl[2][BM][KS];
    uint32_t wh[2][NEXP][KS];
    uint32_t wl[2][NEXP][KS];
};
struct EpiBufs {
    float  lg[BM][NEXP + 1];
    float  qv[BM][NEXP + 1];
    float  red[4][NEXP];
    float  exlog[NEXP];
    int    flagCnt;
    int    flagRows[BM];
};
union SmemU { GemmBufs g; EpiBufs e; };

__device__ __forceinline__ void split_tf32(float v, uint32_t &hi, uint32_t &lo)
{
    asm("cvt.rna.tf32.f32 %0, %1;" : "=r"(hi) : "f"(v));
    float r = v - __uint_as_float(hi);
    asm("cvt.rna.tf32.f32 %0, %1;" : "=r"(lo) : "f"(r));
}

__device__ __forceinline__ void split_store4(uint32_t* hp, uint32_t* lp, float4 v)
{
    uint32_t h0, h1, h2, h3, l0, l1, l2, l3;
    split_tf32(v.x, h0, l0); split_tf32(v.y, h1, l1);
    split_tf32(v.z, h2, l2); split_tf32(v.w, h3, l3);
    *reinterpret_cast<uint4*>(hp) = make_uint4(h0, h1, h2, h3);
    *reinterpret_cast<uint4*>(lp) = make_uint4(l0, l1, l2, l3);
}

__device__ __forceinline__ void mma_tf32(float &c0, float &c1, float &c2, float &c3,
                                         uint32_t a0, uint32_t a1, uint32_t a2, uint32_t a3,
                                         uint32_t b0, uint32_t b1)
{
    asm volatile(
        "mma.sync.aligned.m16n8k8.row.col.f32.tf32.tf32.f32 "
        "{%0,%1,%2,%3}, {%4,%5,%6,%7}, {%8,%9}, {%0,%1,%2,%3};\n"
        : "+f"(c0), "+f"(c1), "+f"(c2), "+f"(c3)
        : "r"(a0), "r"(a1), "r"(a2), "r"(a3), "r"(b0), "r"(b1));
}

// TwoProd + Kahan step (validated R12): effective sum = s - c.
__device__ __forceinline__ void comp_fma(float xv, float wv, float &s, float &c)
{
    float p = xv * wv;
    float e = fmaf(xv, wv, -p);
    float y = p - c;
    float t = s + y;
    c = (t - s) - y;
    c -= e;
    s = t;
}

#define CP_ASYNC16(dst_u32, src_ptr) \
    asm volatile("cp.async.cg.shared.global [%0], [%1], 16;" \
                 :: "r"(dst_u32), "l"(src_ptr))
#define CP_COMMIT() asm volatile("cp.async.commit_group;")
#define CP_WAIT0()  asm volatile("cp.async.wait_group 0;")

__global__ void split_w_kernel(const float* __restrict__ w)
{
    int idx = blockIdx.x * blockDim.x + threadIdx.x;
    if (idx < NEXP * HID) {
        uint32_t hi, lo;
        split_tf32(w[idx], hi, lo);
        (&g_wh[0][0])[idx] = hi;
        (&g_wl[0][0])[idx] = lo;
    }
}

__global__ __launch_bounds__(NTHREADS, 2)
void router_kernel(const float* __restrict__ x,
                   const float* __restrict__ w,
                   float* __restrict__ out,
                   int T)
{
    extern __shared__ char smraw[];
    SmemU& S = *reinterpret_cast<SmemU*>(smraw);

    const int tid  = threadIdx.x;
    const int lane = tid & 31;
    const int wid  = tid >> 5;         // 8 warps
    const int rg   = wid & 3;          // rows rg*16 .. +15
    const int cg   = wid >> 2;         // experts cg*32 .. +31
    const int lr   = lane >> 2;        // 0..7
    const int lc   = lane & 3;         // 0..3
    const int rowBase = blockIdx.x * BM;

    float accP[4][4], accQ[4][4];
#pragma unroll
    for (int i = 0; i < 4; i++)
#pragma unroll
        for (int j = 0; j < 4; j++) { accP[i][j] = 0.0f; accQ[i][j] = 0.0f; }

    // x tile: 64 rows x 8 float4 = 512 float4; thread covers f0 and f1.
    const int f0 = tid, f1 = tid + NTHREADS;
    const int r0 = f0 >> 3, q0 = f0 & 7;
    const int r1 = f1 >> 3, q1 = f1 & 7;

    const float4* __restrict__ xg = (const float4*)x;   // row stride 512
    const float4* __restrict__ wg = (const float4*)w;

    // W tile via cp.async: per plane 64 rows x 8 chunks(16B); 2 chunks/thread/plane.
    const int wr_ = tid >> 2;                 // row 0..63
    const int j0  = (tid & 3) * 2;            // chunk 0..7 (even)
    const int j1  = j0 + 1;

    float4 xr0 = xg[(size_t)(rowBase + r0) * (HID / 4) + q0];
    float4 xr1 = xg[(size_t)(rowBase + r1) * (HID / 4) + q1];

    // ── Prologue: stage 0 ───────────────────────────────────────────────
    {
        uint32_t dh0 = (uint32_t)__cvta_generic_to_shared(&S.g.wh[0][wr_][j0 * 4]);
        uint32_t dh1 = (uint32_t)__cvta_generic_to_shared(&S.g.wh[0][wr_][j1 * 4]);
        uint32_t dl0 = (uint32_t)__cvta_generic_to_shared(&S.g.wl[0][wr_][j0 * 4]);
        uint32_t dl1 = (uint32_t)__cvta_generic_to_shared(&S.g.wl[0][wr_][j1 * 4]);
        CP_ASYNC16(dh0, &g_wh[wr_][j0 * 4]);
        CP_ASYNC16(dh1, &g_wh[wr_][j1 * 4]);
        CP_ASYNC16(dl0, &g_wl[wr_][j0 * 4]);
        CP_ASYNC16(dl1, &g_wl[wr_][j1 * 4]);
        CP_COMMIT();

        split_store4(&S.g.xh[0][r0][q0 * 4], &S.g.xl[0][r0][q0 * 4], xr0);
        split_store4(&S.g.xh[0][r1][q1 * 4], &S.g.xl[0][r1][q1 * 4], xr1);
        CP_WAIT0();
    }
    __syncthreads();

    const int NT = HID / BK;           // 64 K-tiles
    for (int t = 0; t < NT; t++) {
        const int st = t & 1;
        const int sn = st ^ 1;

        if (t + 1 < NT) {
            const int ko = (t + 1) * BK;       // k offset (elements)
            // Kick W(t+1) cp.async into the other stage (overlaps consume)
            uint32_t dh0 = (uint32_t)__cvta_generic_to_shared(&S.g.wh[sn][wr_][j0 * 4]);
            uint32_t dh1 = (uint32_t)__cvta_generic_to_shared(&S.g.wh[sn][wr_][j1 * 4]);
            uint32_t dl0 = (uint32_t)__cvta_generic_to_shared(&S.g.wl[sn][wr_][j0 * 4]);
            uint32_t dl1 = (uint32_t)__cvta_generic_to_shared(&S.g.wl[sn][wr_][j1 * 4]);
            CP_ASYNC16(dh0, &g_wh[wr_][ko + j0 * 4]);
            CP_ASYNC16(dh1, &g_wh[wr_][ko + j1 * 4]);
            CP_ASYNC16(dl0, &g_wl[wr_][ko + j0 * 4]);
            CP_ASYNC16(dl1, &g_wl[wr_][ko + j1 * 4]);
            CP_COMMIT();
            xr0 = xg[(size_t)(rowBase + r0) * (HID / 4) + (ko / 4) + q0];
            xr1 = xg[(size_t)(rowBase + r1) * (HID / 4) + (ko / 4) + q1];
        }

        // Consume stage st: pure LDS.32 (conflict-free) -> HMMA  [R12-identical]
#pragma unroll
        for (int ks_ = 0; ks_ < BK / 8; ks_++) {
            const int kb  = ks_ * 8;
            const int ra0 = rg * 16 + lr, ra1 = ra0 + 8;

            uint32_t ah0 = S.g.xh[st][ra0][kb + lc];
            uint32_t ah1 = S.g.xh[st][ra1][kb + lc];
            uint32_t ah2 = S.g.xh[st][ra0][kb + lc + 4];
            uint32_t ah3 = S.g.xh[st][ra1][kb + lc + 4];
            uint32_t al0 = S.g.xl[st][ra0][kb + lc];
            uint32_t al1 = S.g.xl[st][ra1][kb + lc];
            uint32_t al2 = S.g.xl[st][ra0][kb + lc + 4];
            uint32_t al3 = S.g.xl[st][ra1][kb + lc + 4];

            uint32_t bh[4][2], bl[4][2];
#pragma unroll
            for (int nt = 0; nt < 4; nt++) {
                const int nr = cg * 32 + nt * 8 + lr;
                bh[nt][0] = S.g.wh[st][nr][kb + lc];
                bh[nt][1] = S.g.wh[st][nr][kb + lc + 4];
                bl[nt][0] = S.g.wl[st][nr][kb + lc];
                bl[nt][1] = S.g.wl[st][nr][kb + lc + 4];
            }
#pragma unroll
            for (int nt = 0; nt < 4; nt++)
                mma_tf32(accP[nt][0], accP[nt][1], accP[nt][2], accP[nt][3],
                         ah0, ah1, ah2, ah3, bh[nt][0], bh[nt][1]);
#pragma unroll
            for (int nt = 0; nt < 4; nt++)
                mma_tf32(accQ[nt][0], accQ[nt][1], accQ[nt][2], accQ[nt][3],
                         ah0, ah1, ah2, ah3, bl[nt][0], bl[nt][1]);
#pragma unroll
            for (int nt = 0; nt < 4; nt++)
                mma_tf32(accQ[nt][0], accQ[nt][1], accQ[nt][2], accQ[nt][3],
                         al0, al1, al2, al3, bh[nt][0], bh[nt][1]);
        }

        if (t + 1 < NT) {
            split_store4(&S.g.xh[sn][r0][q0 * 4], &S.g.xl[sn][r0][q0 * 4], xr0);
            split_store4(&S.g.xh[sn][r1][q1 * 4], &S.g.xl[sn][r1][q1 * 4], xr1);
            CP_WAIT0();
        }
        __syncthreads();
    }

    // Dump merged accumulators -> logits (overlays dead GEMM buffers).
#pragma unroll
    for (int nt = 0; nt < 4; nt++) {
        const int col = cg * 32 + nt * 8 + lc * 2;
        S.e.lg[rg * 16 + lr][col]         = accP[nt][0] + accQ[nt][0];
        S.e.lg[rg * 16 + lr][col + 1]     = accP[nt][1] + accQ[nt][1];
        S.e.lg[rg * 16 + lr + 8][col]     = accP[nt][2] + accQ[nt][2];
        S.e.lg[rg * 16 + lr + 8][col + 1] = accP[nt][3] + accQ[nt][3];
    }
    if (tid == 0) S.e.flagCnt = 0;
    __syncthreads();

    // ── Fast epilogue: one thread per row (validated R7..R12) ───────────
    if (tid < BM) {
        const int row = rowBase + tid;

        float m = -1e30f;
#pragma unroll
        for (int e = 0; e < NEXP; e++) m = fmaxf(m, S.e.lg[tid][e]);

        float s = 0.0f;
#pragma unroll
        for (int e = 0; e < NEXP; e++) {
            float d = S.e.lg[tid][e] - m;
            S.e.lg[tid][e] = d;
            float p = expf(d);
            if (p < FLT_MIN_POS) p = 0.0f;       // exp flush (R2->R3 evidence)
            S.e.qv[tid][e] = p;
            s += p;
        }

#pragma unroll
        for (int e = 0; e < NEXP; e++) {
            float q = __fdiv_rn(S.e.qv[tid][e], s);
            if (q < FLT_MIN_POS) q = 0.0f;       // division flush band
            S.e.qv[tid][e] = q;
        }

        unsigned long long mask = 0ull;
        for (int k = 0; k < TOPK; k++) {
            float bv = -1.0f; int bi = 0;
            for (int e = 0; e < NEXP; e++) {
                float v = S.e.qv[tid][e];
                if (!((mask >> e) & 1ull) && v > bv) { bv = v; bi = e; }
            }
            mask |= (1ull << bi);
        }

        // Robustness guard
        int nA = 0;
        float d8 = 1e30f, d9 = -1e30f;
#pragma unroll
        for (int e = 0; e < NEXP; e++) {
            bool pos = S.e.qv[tid][e] > 0.0f;
            bool sel = (mask >> e) & 1ull;
            if (pos) {
                nA++;
                if (sel)  d8 = fminf(d8, S.e.lg[tid][e]);
                else      d9 = fmaxf(d9, S.e.lg[tid][e]);
            }
        }
        bool flag = false;
        if (d9 > -1e29f && (d8 - d9) < GUARD) flag = true;
        if (nA <= 8) {
            float c = logf(s) - EXP_CUT;
#pragma unroll
            for (int e = 0; e < NEXP; e++)
                if (fabsf(S.e.lg[tid][e] - c) < GUARD_CUT) flag = true;
        }

        if (!flag) {
            float* __restrict__ gout = out + (size_t)row * NEXP;
            float* __restrict__ mout = out + (size_t)T * NEXP + (size_t)row * NEXP;
#pragma unroll
            for (int e = 0; e < NEXP; e++) {
                const bool sel = (mask >> e) & 1ull;
                gout[e] = sel ? S.e.qv[tid][e] : 0.0f;
                mout[e] = sel ? 1.0f : 0.0f;
            }
        } else {
            S.e.flagRows[atomicAdd(&S.e.flagCnt, 1)] = tid;
        }
    }
    __syncthreads();

    // ── High-precision fp32 repair (TwoProd + Kahan, validated R12) ─────
    const int nf = S.e.flagCnt;
    for (int r = 0; r < nf; r++) {
        const int lrow = S.e.flagRows[r];
        const int row  = rowBase + lrow;
        const int e    = tid & 63;
        const int ch   = tid >> 6;             // 4 chunks of 512 elements

        const float4* xr = xg + (size_t)row * (HID / 4) + ch * 128;
        const float4* wr = wg + (size_t)e   * (HID / 4) + ch * 128;
        float s0 = 0.f, cc0 = 0.f, s1 = 0.f, cc1 = 0.f;
        float s2 = 0.f, cc2 = 0.f, s3 = 0.f, cc3 = 0.f;
#pragma unroll 4
        for (int i = 0; i < 128; i++) {
            float4 xv = xr[i], wv = wr[i];
            comp_fma(xv.x, wv.x, s0, cc0);
            comp_fma(xv.y, wv.y, s1, cc1);
            comp_fma(xv.z, wv.z, s2, cc2);
            comp_fma(xv.w, wv.w, s3, cc3);
        }
        S.e.red[ch][e] = ((s0 - cc0) + (s1 - cc1)) + ((s2 - cc2) + (s3 - cc3));
        __syncthreads();
        if (tid < NEXP)
            S.e.exlog[tid] = (S.e.red[0][tid] + S.e.red[1][tid]) +
                             (S.e.red[2][tid] + S.e.red[3][tid]);
        __syncthreads();

        if (tid == 0) {
            float m = -1e30f;
            for (int ee = 0; ee < NEXP; ee++) m = fmaxf(m, S.e.exlog[ee]);
            float s = 0.0f;
            float pbuf[NEXP];
            for (int ee = 0; ee < NEXP; ee++) {
                float p = expf(S.e.exlog[ee] - m);
                if (p < FLT_MIN_POS) p = 0.0f;
                pbuf[ee] = p;
                s += p;
            }
            for (int ee = 0; ee < NEXP; ee++) {
                float q = __fdiv_rn(pbuf[ee], s);
                if (q < FLT_MIN_POS) q = 0.0f;
                pbuf[ee] = q;
            }
            unsigned long long mask = 0ull;
            for (int k = 0; k < TOPK; k++) {
                float bv = -1.0f; int bi = 0;
                for (int ee = 0; ee < NEXP; ee++) {
                    float v = pbuf[ee];
                    if (!((mask >> ee) & 1ull) && v > bv) { bv = v; bi = ee; }
                }
                mask |= (1ull << bi);
            }
            float* __restrict__ gout = out + (size_t)row * NEXP;
            float* __restrict__ mout = out + (size_t)T * NEXP + (size_t)row * NEXP;
            for (int ee = 0; ee < NEXP; ee++) {
                const bool sel = (mask >> ee) & 1ull;
                gout[ee] = sel ? pbuf[ee] : 0.0f;
                mout[ee] = sel ? 1.0f : 0.0f;
            }
        }
        __syncthreads();
    }
}

extern "C" void kernel_launch(void* const* d_in, const int* in_sizes, int n_in,
                              void* d_out, int out_size)
{
    const float* x = (const float*)d_in[0];
    const float* w = (const float*)d_in[1];
    float* out = (float*)d_out;
    const int T = in_sizes[0] / HID;       // 16384
    const int grid = T / BM;               // 256

    split_w_kernel<<<(NEXP * HID + 255) / 256, 256>>>(w);

    const int smem = (int)sizeof(SmemU);   // ~73 KB
    cudaFuncSetAttribute(router_kernel,
                         cudaFuncAttributeMaxDynamicSharedMemorySize, smem);
    router_kernel<<<grid, NTHREADS, smem>>>(x, w, out, T);
}